// round 1
// baseline (speedup 1.0000x reference)
#include <cuda_runtime.h>
#include <math.h>
#include <math_constants.h>

// QuadraticLorentzAttention: causal Lorentz (Minkowski) attention.
// B*H = 32, N = 2048, D = 65 (Lorentz), fp32.
// scores = <Q', K> with Q'_0 = -Q_0; causal softmax; y = P @ V;
// out[...,0] = sqrt(||y[...,1:]||^2 + 1), out[...,1:] = y[...,1:].

namespace {
constexpr int N_SEQ = 2048;
constexpr int D     = 65;
constexpr int DP    = 68;   // padded to float4 multiple
constexpr int NV    = 17;   // DP/4 float4s
constexpr int BQ    = 64;   // queries per block (1 per thread)
constexpr int BK    = 64;   // key tile
}

__global__ void __launch_bounds__(BQ)
lorentz_attn_kernel(const float* __restrict__ Qg,
                    const float* __restrict__ Kg,
                    const float* __restrict__ Vg,
                    const int* __restrict__ causal_p,
                    float* __restrict__ Og)
{
    __shared__ float4 ks4[BK * NV];
    __shared__ float4 vs4[BK * NV];
    float* ksf = reinterpret_cast<float*>(ks4);
    float* vsf = reinterpret_cast<float*>(vs4);

    const int tid = threadIdx.x;
    const int bh  = blockIdx.y;
    const int q0  = blockIdx.x * BQ;
    const int qi  = q0 + tid;
    const size_t base = (size_t)bh * N_SEQ * D;

    // zero the pad columns once (never overwritten by tile loads, d < 65)
    ksf[tid * DP + 65] = 0.f; ksf[tid * DP + 66] = 0.f; ksf[tid * DP + 67] = 0.f;
    vsf[tid * DP + 65] = 0.f; vsf[tid * DP + 66] = 0.f; vsf[tid * DP + 67] = 0.f;

    // load this thread's query row, negate time component
    float q_r[DP];
    {
        const float* qrow = Qg + base + (size_t)qi * D;
        #pragma unroll
        for (int d = 0; d < D; d++) q_r[d] = qrow[d];
        q_r[0] = -q_r[0];
        q_r[65] = 0.f; q_r[66] = 0.f; q_r[67] = 0.f;
    }

    float4 acc[NV];
    #pragma unroll
    for (int i = 0; i < NV; i++) acc[i] = make_float4(0.f, 0.f, 0.f, 0.f);
    float m = -CUDART_INF_F;
    float l = 0.f;

    const int cz = *causal_p;
    const int kend = cz ? (q0 + BQ) : N_SEQ;

    for (int k0 = 0; k0 < kend; k0 += BK) {
        __syncthreads();
        // K/V tile rows are contiguous in gmem (last dim contiguous, stride D):
        // load BK*D contiguous floats coalesced, scatter into DP-padded smem.
        const float* kp = Kg + base + (size_t)k0 * D;
        const float* vp = Vg + base + (size_t)k0 * D;
        for (int idx = tid; idx < BK * D; idx += BQ) {
            const int r = idx / D;
            const int d = idx - r * D;
            ksf[r * DP + d] = kp[idx];
            vsf[r * DP + d] = vp[idx];
        }
        __syncthreads();

        int jmax = cz ? (qi - k0 + 1) : BK;
        if (jmax > BK) jmax = BK;

        #pragma unroll 2
        for (int j = 0; j < BK; j++) {
            // score: 4 independent FMA chains for ILP
            float s0 = 0.f, s1 = 0.f, s2 = 0.f, s3 = 0.f;
            #pragma unroll
            for (int i = 0; i < NV; i++) {
                const float4 k4 = ks4[j * NV + i];
                s0 = fmaf(q_r[4*i + 0], k4.x, s0);
                s1 = fmaf(q_r[4*i + 1], k4.y, s1);
                s2 = fmaf(q_r[4*i + 2], k4.z, s2);
                s3 = fmaf(q_r[4*i + 3], k4.w, s3);
            }
            float s = (s0 + s1) + (s2 + s3);
            if (j >= jmax) s = -CUDART_INF_F;   // causal mask (j=0 always valid -> no NaN)

            const float m_new = fmaxf(m, s);
            const float p = __expf(s - m_new);

            if (__all_sync(0xffffffffu, m_new == m)) {
                // fast path: running max unchanged warp-wide -> no rescale
                l += p;
                #pragma unroll
                for (int i = 0; i < NV; i++) {
                    const float4 v4 = vs4[j * NV + i];
                    acc[i].x = fmaf(p, v4.x, acc[i].x);
                    acc[i].y = fmaf(p, v4.y, acc[i].y);
                    acc[i].z = fmaf(p, v4.z, acc[i].z);
                    acc[i].w = fmaf(p, v4.w, acc[i].w);
                }
            } else {
                const float corr = __expf(m - m_new);
                l = fmaf(l, corr, p);
                m = m_new;
                #pragma unroll
                for (int i = 0; i < NV; i++) {
                    const float4 v4 = vs4[j * NV + i];
                    acc[i].x = fmaf(p, v4.x, acc[i].x * corr);
                    acc[i].y = fmaf(p, v4.y, acc[i].y * corr);
                    acc[i].z = fmaf(p, v4.z, acc[i].z * corr);
                    acc[i].w = fmaf(p, v4.w, acc[i].w * corr);
                }
            }
        }
    }

    // epilogue: normalize, recompute time coordinate, write out
    const float inv_l = 1.0f / l;
    #pragma unroll
    for (int i = 0; i < NV; i++) {
        acc[i].x *= inv_l; acc[i].y *= inv_l; acc[i].z *= inv_l; acc[i].w *= inv_l;
    }
    float ss = 0.f;
    #pragma unroll
    for (int i = 0; i < NV; i++) {
        ss += acc[i].x * acc[i].x + acc[i].y * acc[i].y
            + acc[i].z * acc[i].z + acc[i].w * acc[i].w;
    }
    ss -= acc[0].x * acc[0].x;          // exclude weighted time coord (pads are 0)
    const float t = sqrtf(ss + 1.0f);   // -1/K with K=-1

    float* orow = Og + base + (size_t)qi * D;
    #pragma unroll
    for (int i = 0; i < NV; i++) {
        const int d = 4 * i;
        if (d > 0 && d < D)  orow[d]     = acc[i].x;
        if (d + 1 < D)       orow[d + 1] = acc[i].y;
        if (d + 2 < D)       orow[d + 2] = acc[i].z;
        if (d + 3 < D)       orow[d + 3] = acc[i].w;
    }
    orow[0] = t;
}

extern "C" void kernel_launch(void* const* d_in, const int* in_sizes, int n_in,
                              void* d_out, int out_size)
{
    const float* Q  = (const float*)d_in[0];
    const float* K  = (const float*)d_in[1];
    const float* V  = (const float*)d_in[2];
    const int* causal = (const int*)d_in[3];
    float* out = (float*)d_out;

    const int BH = in_sizes[0] / (N_SEQ * D);   // 32
    dim3 grid(N_SEQ / BQ, BH);
    dim3 block(BQ);
    lorentz_attn_kernel<<<grid, block>>>(Q, K, V, causal, out);
}